// round 1
// baseline (speedup 1.0000x reference)
#include <cuda_runtime.h>
#include <cuda_bf16.h>

// BodyKinematics: batched tree forward kinematics.
//   Inputs (metadata order):
//     0: log_angles      (B, 3E)  float32      B=4096, E=255
//     1: tip_to_base     (E, 4, 4) float32
//     2: rot_axes        (3E, 3)  float32
//     3: rot_constraints (3E, 2)  float32  [scale, offset]
//   Output: (B, N, 4, 4) float32, N = E+1 = 256
//
// One CTA per batch element, 256 threads. Thread e (<255) builds the local
// affine transform for edge e; then 8 level-parallel tree-composition steps
// in shared memory; each thread writes its node's 4x4 as 4x STG.128.

#define NN 256
#define EE 255

__global__ __launch_bounds__(256) void fk_kernel(
    const float* __restrict__ la,    // (B, 3E)
    const float* __restrict__ tip,   // (E,4,4)
    const float* __restrict__ axes,  // (3E,3)
    const float* __restrict__ cons,  // (3E,2)
    float* __restrict__ out)         // (B,N,4,4)
{
    // Row stride 13 (odd) -> conflict-free shared access for 12-float records.
    __shared__ float loc[EE][13];   // local affine per edge: 3x4 row-major
    __shared__ float wrd[NN][13];   // world affine per node: 3x4 row-major

    const int b = blockIdx.x;
    const int t = threadIdx.x;

    if (t < EE) {
        const int e = t;
        const float* lap = la + (size_t)b * (3 * EE) + 3 * e;

        float M[9];
        #pragma unroll
        for (int j = 0; j < 3; ++j) {
            const int idx = 3 * e + j;
            const float sc = __ldg(&cons[2 * idx]);
            const float of = __ldg(&cons[2 * idx + 1]);
            const float th = tanhf(lap[j]) * sc + of;
            float sn, cs;
            sincosf(th, &sn, &cs);
            const float ax = __ldg(&axes[3 * idx]);
            const float ay = __ldg(&axes[3 * idx + 1]);
            const float az = __ldg(&axes[3 * idx + 2]);
            const float C = 1.0f - cs;
            // Rodrigues: R = c I + s [a]x + (1-c) a a^T   (a is unit)
            float R[9];
            R[0] = cs + C * ax * ax;  R[1] = C * ax * ay - sn * az;  R[2] = C * ax * az + sn * ay;
            R[3] = C * ax * ay + sn * az;  R[4] = cs + C * ay * ay;  R[5] = C * ay * az - sn * ax;
            R[6] = C * ax * az - sn * ay;  R[7] = C * ay * az + sn * ax;  R[8] = cs + C * az * az;

            if (j == 0) {
                #pragma unroll
                for (int k = 0; k < 9; ++k) M[k] = R[k];
            } else {
                float Mn[9];
                #pragma unroll
                for (int r = 0; r < 3; ++r)
                    #pragma unroll
                    for (int c = 0; c < 3; ++c)
                        Mn[3 * r + c] = M[3 * r + 0] * R[c]
                                      + M[3 * r + 1] * R[3 + c]
                                      + M[3 * r + 2] * R[6 + c];
                #pragma unroll
                for (int k = 0; k < 9; ++k) M[k] = Mn[k];
            }
        }

        // local = [M|0;0 1] @ tip  -> top 3 rows: M @ tip[:3,:4]
        const float* tp = tip + 16 * e;
        #pragma unroll
        for (int r = 0; r < 3; ++r) {
            #pragma unroll
            for (int c = 0; c < 4; ++c) {
                loc[e][4 * r + c] = M[3 * r + 0] * __ldg(&tp[c])
                                  + M[3 * r + 1] * __ldg(&tp[4 + c])
                                  + M[3 * r + 2] * __ldg(&tp[8 + c]);
            }
        }
    } else {
        // t == 255: root world = identity
        #pragma unroll
        for (int k = 0; k < 12; ++k) wrd[0][k] = 0.0f;
        wrd[0][0] = 1.0f; wrd[0][5] = 1.0f; wrd[0][10] = 1.0f;
    }
    __syncthreads();

    // Level-parallel tree FK. Levels: [1,3),[3,7),...,[127,255),[255,256).
    #pragma unroll
    for (int lo = 1; lo < NN; lo = 2 * lo + 1) {
        const int hi = (2 * lo + 1 < NN) ? (2 * lo + 1) : NN;
        if (t >= lo && t < hi) {
            const int p = (t - 1) >> 1;
            const float* P = wrd[p];
            const float* L = loc[t - 1];
            float W[12];
            #pragma unroll
            for (int r = 0; r < 3; ++r) {
                #pragma unroll
                for (int c = 0; c < 4; ++c) {
                    float v = P[4 * r + 0] * L[c]
                            + P[4 * r + 1] * L[4 + c]
                            + P[4 * r + 2] * L[8 + c];
                    if (c == 3) v += P[4 * r + 3];
                    W[4 * r + c] = v;
                }
            }
            #pragma unroll
            for (int k = 0; k < 12; ++k) wrd[t][k] = W[k];
        }
        __syncthreads();
    }

    // Write node t's 4x4 (row-major) as 4x float4.
    float4* o = (float4*)(out + ((size_t)b * NN + t) * 16);
    o[0] = make_float4(wrd[t][0], wrd[t][1], wrd[t][2], wrd[t][3]);
    o[1] = make_float4(wrd[t][4], wrd[t][5], wrd[t][6], wrd[t][7]);
    o[2] = make_float4(wrd[t][8], wrd[t][9], wrd[t][10], wrd[t][11]);
    o[3] = make_float4(0.0f, 0.0f, 0.0f, 1.0f);
}

extern "C" void kernel_launch(void* const* d_in, const int* in_sizes, int n_in,
                              void* d_out, int out_size) {
    const float* la   = (const float*)d_in[0];   // (B, 3E)
    const float* tip  = (const float*)d_in[1];   // (E,4,4)
    const float* axes = (const float*)d_in[2];   // (3E,3)
    const float* cons = (const float*)d_in[3];   // (3E,2)
    float* out = (float*)d_out;

    const int B = in_sizes[0] / (3 * EE);        // 4096
    fk_kernel<<<B, NN>>>(la, tip, axes, cons, out);
}

// round 2
// speedup vs baseline: 1.8099x; 1.8099x over previous
#include <cuda_runtime.h>
#include <cuda_bf16.h>

// BodyKinematics: batched tree forward kinematics. B=4096, N=256, E=255.
// Round 2: register-resident locals, float4 everywhere, direct STG from the
// tree level, packed per-edge constants via prepass, fast transcendentals.

#define NN 256
#define EE 255

// Packed per-edge constants: [T0,T1,T2, (ax0|sc0),(ax1|sc1),(ax2|sc2),(of0,of1,of2,0)]
__device__ float4 g_cst[EE * 7];

__global__ void pack_kernel(const float* __restrict__ tip,
                            const float* __restrict__ axes,
                            const float* __restrict__ cons) {
    int e = blockIdx.x * blockDim.x + threadIdx.x;
    if (e >= EE) return;
    float4* o = g_cst + e * 7;
    const float4* tp = (const float4*)(tip + 16 * e);
    o[0] = tp[0]; o[1] = tp[1]; o[2] = tp[2];
    #pragma unroll
    for (int j = 0; j < 3; ++j) {
        int idx = 3 * e + j;
        o[3 + j] = make_float4(axes[3 * idx], axes[3 * idx + 1], axes[3 * idx + 2],
                               cons[2 * idx]);
    }
    o[6] = make_float4(cons[2 * (3 * e) + 1], cons[2 * (3 * e + 1) + 1],
                       cons[2 * (3 * e + 2) + 1], 0.0f);
}

__device__ __forceinline__ float ftanh(float x) {
    float ax = fabsf(x);
    float t = __expf(2.0f * ax);
    float r = __fdividef(t - 1.0f, t + 1.0f);
    r = ax > 40.0f ? 1.0f : r;
    return copysignf(r, x);
}

// world_row = P.x*L0 + P.y*L1 + P.z*L2 (+ P.w in translation slot)
__device__ __forceinline__ float4 aff(float4 P, float4 L0, float4 L1, float4 L2) {
    float4 w;
    w.x = fmaf(P.x, L0.x, fmaf(P.y, L1.x, P.z * L2.x));
    w.y = fmaf(P.x, L0.y, fmaf(P.y, L1.y, P.z * L2.y));
    w.z = fmaf(P.x, L0.z, fmaf(P.y, L1.z, P.z * L2.z));
    w.w = fmaf(P.x, L0.w, fmaf(P.y, L1.w, fmaf(P.z, L2.w, P.w)));
    return w;
}

__global__ __launch_bounds__(256) void fk_kernel(
    const float* __restrict__ la,    // (B, 3E)
    float* __restrict__ out)         // (B, N, 4, 4)
{
    __shared__ float4 wA[128], wB[128], wC[128];  // world rows for nodes 0..127

    const int b = blockIdx.x;
    const int t = threadIdx.x;

    float4 L0, L1, L2;  // local affine rows for node t (edge t-1), registers only

    if (t > 0) {
        const int e = t - 1;
        const float* lap = la + (size_t)b * (3 * EE) + 3 * e;
        const float x0 = lap[0], x1 = lap[1], x2 = lap[2];

        const float4* cp = g_cst + e * 7;
        const float4 T0 = cp[0], T1 = cp[1], T2 = cp[2];
        const float4 A0 = cp[3], A1 = cp[4], A2 = cp[5], OF = cp[6];

        const float th0 = ftanh(x0) * A0.w + OF.x;
        const float th1 = ftanh(x1) * A1.w + OF.y;
        const float th2 = ftanh(x2) * A2.w + OF.z;

        float R0[9], R1[9], R2[9];
        {
            float s, c;
            __sincosf(th0, &s, &c);
            const float C = 1.0f - c, ax = A0.x, ay = A0.y, az = A0.z;
            R0[0] = c + C * ax * ax; R0[1] = C * ax * ay - s * az; R0[2] = C * ax * az + s * ay;
            R0[3] = C * ax * ay + s * az; R0[4] = c + C * ay * ay; R0[5] = C * ay * az - s * ax;
            R0[6] = C * ax * az - s * ay; R0[7] = C * ay * az + s * ax; R0[8] = c + C * az * az;
        }
        {
            float s, c;
            __sincosf(th1, &s, &c);
            const float C = 1.0f - c, ax = A1.x, ay = A1.y, az = A1.z;
            R1[0] = c + C * ax * ax; R1[1] = C * ax * ay - s * az; R1[2] = C * ax * az + s * ay;
            R1[3] = C * ax * ay + s * az; R1[4] = c + C * ay * ay; R1[5] = C * ay * az - s * ax;
            R1[6] = C * ax * az - s * ay; R1[7] = C * ay * az + s * ax; R1[8] = c + C * az * az;
        }
        {
            float s, c;
            __sincosf(th2, &s, &c);
            const float C = 1.0f - c, ax = A2.x, ay = A2.y, az = A2.z;
            R2[0] = c + C * ax * ax; R2[1] = C * ax * ay - s * az; R2[2] = C * ax * az + s * ay;
            R2[3] = C * ax * ay + s * az; R2[4] = c + C * ay * ay; R2[5] = C * ay * az - s * ax;
            R2[6] = C * ax * az - s * ay; R2[7] = C * ay * az + s * ax; R2[8] = c + C * az * az;
        }

        // M = R0 @ R1 @ R2
        float M01[9], M[9];
        #pragma unroll
        for (int r = 0; r < 3; ++r)
            #pragma unroll
            for (int c = 0; c < 3; ++c)
                M01[3 * r + c] = R0[3 * r] * R1[c] + R0[3 * r + 1] * R1[3 + c]
                               + R0[3 * r + 2] * R1[6 + c];
        #pragma unroll
        for (int r = 0; r < 3; ++r)
            #pragma unroll
            for (int c = 0; c < 3; ++c)
                M[3 * r + c] = M01[3 * r] * R2[c] + M01[3 * r + 1] * R2[3 + c]
                             + M01[3 * r + 2] * R2[6 + c];

        // local rows = M @ tip rows (tip row 3 implicit (0,0,0,1), T[:3,3]=0 col handled by tip)
        #define MT(r, D)                                                        \
            D.x = fmaf(M[3*r], T0.x, fmaf(M[3*r+1], T1.x, M[3*r+2] * T2.x));    \
            D.y = fmaf(M[3*r], T0.y, fmaf(M[3*r+1], T1.y, M[3*r+2] * T2.y));    \
            D.z = fmaf(M[3*r], T0.z, fmaf(M[3*r+1], T1.z, M[3*r+2] * T2.z));    \
            D.w = fmaf(M[3*r], T0.w, fmaf(M[3*r+1], T1.w, M[3*r+2] * T2.w));
        MT(0, L0) MT(1, L1) MT(2, L2)
        #undef MT
    } else {
        // thread 0 = root: identity world, write output now
        wA[0] = make_float4(1.f, 0.f, 0.f, 0.f);
        wB[0] = make_float4(0.f, 1.f, 0.f, 0.f);
        wC[0] = make_float4(0.f, 0.f, 1.f, 0.f);
        float4* o = (float4*)(out + (size_t)b * NN * 16);
        o[0] = make_float4(1.f, 0.f, 0.f, 0.f);
        o[1] = make_float4(0.f, 1.f, 0.f, 0.f);
        o[2] = make_float4(0.f, 0.f, 1.f, 0.f);
        o[3] = make_float4(0.f, 0.f, 0.f, 1.f);
    }
    __syncthreads();

    // Level-parallel tree: lo = 1,3,7,15,31,63,127,255
    #pragma unroll
    for (int lo = 1; lo < NN; lo = 2 * lo + 1) {
        const int hi = (2 * lo + 1 < NN) ? (2 * lo + 1) : NN;
        if (t >= lo && t < hi) {
            const int p = (t - 1) >> 1;
            const float4 P0 = wA[p], P1 = wB[p], P2 = wC[p];
            const float4 W0 = aff(P0, L0, L1, L2);
            const float4 W1 = aff(P1, L0, L1, L2);
            const float4 W2 = aff(P2, L0, L1, L2);
            if (t < 128) { wA[t] = W0; wB[t] = W1; wC[t] = W2; }
            float4* o = (float4*)(out + ((size_t)b * NN + t) * 16);
            o[0] = W0; o[1] = W1; o[2] = W2;
            o[3] = make_float4(0.f, 0.f, 0.f, 1.f);
        }
        if (2 * lo + 1 < NN) __syncthreads();
    }
}

extern "C" void kernel_launch(void* const* d_in, const int* in_sizes, int n_in,
                              void* d_out, int out_size) {
    const float* la   = (const float*)d_in[0];
    const float* tip  = (const float*)d_in[1];
    const float* axes = (const float*)d_in[2];
    const float* cons = (const float*)d_in[3];
    float* out = (float*)d_out;

    const int B = in_sizes[0] / (3 * EE);
    pack_kernel<<<1, 256>>>(tip, axes, cons);
    fk_kernel<<<B, NN>>>(la, out);
}